// round 16
// baseline (speedup 1.0000x reference)
#include <cuda_runtime.h>

#define DIM    256    // DIM_IN
#define BATCH  1024   // B
#define NI     32640  // C(256,2)

#define TT     32     // i/j tile size (8 tiles of 32)
#define ROWS   64     // batch rows per item
#define ITEMS  2      // y-items per block (fused in one mainloop)
#define NPAIR  36     // unordered tile pairs
#define XP     36     // x tile pitch in floats

__constant__ unsigned char cTI[NPAIR] = {0,0,0,0,0,0,0,0, 1,1,1,1,1,1,1, 2,2,2,2,2,2,
                                         3,3,3,3,3, 4,4,4,4, 5,5,5, 6,6, 7};
__constant__ unsigned char cTJ[NPAIR] = {0,1,2,3,4,5,6,7, 1,2,3,4,5,6,7, 2,3,4,5,6,7,
                                         3,4,5,6,7, 4,5,6,7, 5,6,7, 6,7, 7};

__global__ void zero_out_kernel(float* __restrict__ out) {
    out[blockIdx.x * 256 + threadIdx.x] = 0.0f;   // 4 blocks x 256
}

// Packed f32x2 FMA
__device__ __forceinline__ float2 fma2(float2 a, float2 b, float2 c) {
    float2 d;
    asm("fma.rn.f32x2 %0, %1, %2, %3;"
        : "=l"(*reinterpret_cast<unsigned long long*>(&d))
        : "l"(*reinterpret_cast<const unsigned long long*>(&a)),
          "l"(*reinterpret_cast<const unsigned long long*>(&b)),
          "l"(*reinterpret_cast<const unsigned long long*>(&c)));
    return d;
}

// 16B global->shared async copy (LDGSTS)
__device__ __forceinline__ void cp_async16(unsigned smem_addr, const void* gptr) {
    asm volatile("cp.async.ca.shared.global [%0], [%1], 16;"
                 :: "r"(smem_addr), "l"(__cvta_generic_to_global(gptr)) : "memory");
}

// out[b] = sum_{i<j} (w0+w1)*w0*w1 * x[b,i]*x[b,j]
// Block = one unordered tile pair x 2 FUSED 64-row items.
// Thread tile: 1 row x 2 items x 8 j -> per i-step: 2 LDS.128 + 2 LDS for
// 8 FFMA2 across two independent accumulator sets (FMA:load issue 8:4).
__global__ void __launch_bounds__(256, 2)
quad_kernel(const float* __restrict__ x, const float* __restrict__ w,
            float* __restrict__ out) {
    __shared__ __align__(16) float As[TT * TT];                 // 4KB
    __shared__ __align__(16) float xIb[ITEMS][ROWS * XP];       // 2 x 9.2KB
    __shared__ __align__(16) float xJb[ITEMS][ROWS * XP];       // 2 x 9.2KB

    const int t     = threadIdx.x;
    const int pair  = blockIdx.x;
    const int ibase = cTI[pair] * TT;
    const int jbase = cTJ[pair] * TT;
    const int rbase = blockIdx.y * (ROWS * ITEMS);

    // ---- Issue BOTH items' x tiles via cp.async.
#pragma unroll
    for (int item = 0; item < ITEMS; ++item) {
        const unsigned sI = (unsigned)__cvta_generic_to_shared(xIb[item]);
        const unsigned sJ = (unsigned)__cvta_generic_to_shared(xJb[item]);
        const int rb = rbase + item * ROWS;
#pragma unroll
        for (int s = 0; s < 2; ++s) {
            const int c  = s * 256 + t;
            const int r  = c >> 3, cc = c & 7;       // 64 rows x 8 16B-chunks
            const long rowoff = (long)(rb + r) * DIM;
            cp_async16(sI + (r * XP + cc * 4) * 4, x + rowoff + ibase + cc * 4);
            cp_async16(sJ + (r * XP + cc * 4) * 4, x + rowoff + jbase + cc * 4);
        }
    }
    asm volatile("cp.async.commit_group;" ::: "memory");

    // ---- A tile (shared by both items): batched coalesced w loads, then STS.
    float w0v[4], w1v[4];
    bool  val[4];
#pragma unroll
    for (int s = 0; s < 4; ++s) {
        const int idx = s * 256 + t;
        const int gi = ibase + (idx >> 5);
        const int gj = jbase + (idx & 31);
        val[s] = (gj > gi);
        const int k = val[s] ? (gi * 255 - (gi * (gi - 1)) / 2 + (gj - gi - 1)) : 0;
        w0v[s] = __ldg(&w[k]);
        w1v[s] = __ldg(&w[NI + k]);
    }
#pragma unroll
    for (int s = 0; s < 4; ++s) {
        const int idx = s * 256 + t;
        As[idx] = val[s] ? (w0v[s] + w1v[s]) * w0v[s] * w1v[s] : 0.0f;
    }

    asm volatile("cp.async.wait_group 0;" ::: "memory");
    __syncthreads();   // the ONLY block barrier

    // ---- Thread tile: 1 row x 2 items x 8 j (4-lane j-groups).
    const int jg = t & 3;             // 4 j-groups x 8 j = 32 j
    const int j0 = jg * 8;
    const int r0 = t >> 2;            // 64 rows, 1 per thread per item

    const float* xI0 = xIb[0] + r0 * XP;
    const float* xI1 = xIb[1] + r0 * XP;

    float2 b0 = {0.f,0.f}, b1 = {0.f,0.f}, b2 = {0.f,0.f}, b3 = {0.f,0.f};  // item 0
    float2 c0 = {0.f,0.f}, c1 = {0.f,0.f}, c2 = {0.f,0.f}, c3 = {0.f,0.f};  // item 1

#pragma unroll
    for (int i = 0; i < TT; ++i) {
        const float4 avL = *reinterpret_cast<const float4*>(&As[i * TT + j0]);      // j0..j0+3
        const float4 avH = *reinterpret_cast<const float4*>(&As[i * TT + j0 + 4]);  // j0+4..j0+7
        const float u = xI0[i];
        const float v = xI1[i];
        const float2 A01 = make_float2(avL.x, avL.y);
        const float2 A23 = make_float2(avL.z, avL.w);
        const float2 A45 = make_float2(avH.x, avH.y);
        const float2 A67 = make_float2(avH.z, avH.w);
        const float2 ud = make_float2(u, u);
        const float2 vd = make_float2(v, v);
        b0 = fma2(ud, A01, b0);
        c0 = fma2(vd, A01, c0);
        b1 = fma2(ud, A23, b1);
        c1 = fma2(vd, A23, c1);
        b2 = fma2(ud, A45, b2);
        c2 = fma2(vd, A45, c2);
        b3 = fma2(ud, A67, b3);
        c3 = fma2(vd, A67, c3);
    }

    // ---- Epilogue: dot with x_J (8 j per thread per item), 4-lane reduce.
    const float4 xj0L = *reinterpret_cast<const float4*>(&xJb[0][r0 * XP + j0]);
    const float4 xj0H = *reinterpret_cast<const float4*>(&xJb[0][r0 * XP + j0 + 4]);
    const float4 xj1L = *reinterpret_cast<const float4*>(&xJb[1][r0 * XP + j0]);
    const float4 xj1H = *reinterpret_cast<const float4*>(&xJb[1][r0 * XP + j0 + 4]);

    float2 sb = fma2(b0, make_float2(xj0L.x, xj0L.y),
               fma2(b1, make_float2(xj0L.z, xj0L.w),
               fma2(b2, make_float2(xj0H.x, xj0H.y),
               fma2(b3, make_float2(xj0H.z, xj0H.w), make_float2(0.f, 0.f)))));
    float2 sc = fma2(c0, make_float2(xj1L.x, xj1L.y),
               fma2(c1, make_float2(xj1L.z, xj1L.w),
               fma2(c2, make_float2(xj1H.x, xj1H.y),
               fma2(c3, make_float2(xj1H.z, xj1H.w), make_float2(0.f, 0.f)))));

    float vb = sb.x + sb.y;
    float vc = sc.x + sc.y;

#pragma unroll
    for (int m = 2; m > 0; m >>= 1) {   // reduce within 4-lane j-groups
        vb += __shfl_xor_sync(0xffffffffu, vb, m, 32);
        vc += __shfl_xor_sync(0xffffffffu, vc, m, 32);
    }
    if (jg == 0) {
        atomicAdd(&out[rbase + r0],        vb);
        atomicAdd(&out[rbase + ROWS + r0], vc);
    }
}

extern "C" void kernel_launch(void* const* d_in, const int* in_sizes, int n_in,
                              void* d_out, int out_size) {
    const float* x = (const float*)d_in[0];
    const float* w = (const float*)d_in[1];
    float* out = (float*)d_out;

    zero_out_kernel<<<4, 256>>>(out);
    quad_kernel<<<dim3(NPAIR, BATCH / (ROWS * ITEMS)), 256>>>(x, w, out);  // 288 blocks
}